// round 16
// baseline (speedup 1.0000x reference)
#include <cuda_runtime.h>
#include <cstdint>

#define BATCH 16384
#define STEPS 32
#define LAT   64
#define IN_W  (STEPS * (2 * LAT + 1) + 2 * LAT)   // 4256 floats per row
#define WARPS_PER_BLOCK 4
#define NTHREADS (WARPS_PER_BLOCK * 32)           // 128
#define ROWS_PER_WARP 2
#define ROWS_PER_BLOCK (WARPS_PER_BLOCK * ROWS_PER_WARP)   // 8
#define NBLOCKS (BATCH / ROWS_PER_BLOCK)                   // 2048
#define BOFF ((2 + 2 * STEPS) * LAT)              // 4224: bias offset in row

#define STAGES 3
#define STAGE_BYTES 1024                          // per warp: u 512B + w 512B (2 rows)
#define WARP_PIPE_BYTES (STAGES * STAGE_BYTES)    // 3 KB per warp
// block smem ~12.3KB -> 10 blocks/SM (123KB), 40 warps/SM (reg-capped at 51/thr)

// scratch for deterministic single-kernel loss reduction (no allocations allowed)
__device__ float g_partials[NBLOCKS];
__device__ unsigned int g_count = 0;   // ticket counter; last block resets to 0

__device__ __forceinline__ void cp16(uint32_t dst_smem, const void* src) {
    asm volatile("cp.async.cg.shared.global [%0], [%1], 16;\n"
                 :: "r"(dst_smem), "l"(src) : "memory");
}
#define CP_COMMIT() asm volatile("cp.async.commit_group;\n" ::: "memory")
#define CP_WAIT2()  asm volatile("cp.async.wait_group 2;\n" ::: "memory")

__global__ void __launch_bounds__(NTHREADS, 10)
planar_flow_kernel(const float* __restrict__ in,
                   const float* __restrict__ noise,
                   float* __restrict__ out, int out_size)
{
    __shared__ __align__(16) unsigned char pipe[WARPS_PER_BLOCK * WARP_PIPE_BYTES]; // 12 KB
    __shared__ float sacc[WARPS_PER_BLOCK];
    __shared__ bool  is_last;

    const int warp = threadIdx.x >> 5;
    const int lane = threadIdx.x & 31;
    const int h    = lane & 15;                    // position within my row's 16-lane group
    const int row  = blockIdx.x * ROWS_PER_BLOCK + warp * ROWS_PER_WARP + (lane >> 4);

    const float* rp = in + (size_t)row * IN_W;     // 17024 B/row: 16B aligned

    // global u/w byte pointers for THIS lane's 16B chunk of each 256B step-block
    const char* Ug = (const char*)(rp + 2 * LAT)           + h * 16;
    const char* Wg = (const char*)(rp + (2 + STEPS) * LAT) + h * 16;

    // smem slot address for this lane (it reads back exactly what it writes)
    const uint32_t wbase = (uint32_t)__cvta_generic_to_shared(pipe) + warp * WARP_PIPE_BYTES;
    const uint32_t loff  = (lane >> 4) * 256 + h * 16;  // within the 512B u (or w) block

    // ---- prologue: prime 3 pipeline stages (memory busy immediately) ----
    #pragma unroll
    for (int st = 0; st < STAGES; st++) {
        uint32_t sb = wbase + st * STAGE_BYTES;
        cp16(sb + loff,        Ug + st * 256);
        cp16(sb + 512 + loff,  Wg + st * 256);
        CP_COMMIT();
    }

    // --- z0 = mu + noise * exp(0.5*logsigma2), 4 elements per lane ---
    const float4* rp4 = (const float4*)rp;
    float4 mu = rp4[h];                                            // floats [0,64)
    float4 ls = rp4[16 + h];                                       // floats [64,128)
    float4 nz = ((const float4*)(noise + (size_t)row * LAT))[h];

    float4 z;
    z.x = mu.x + nz.x * __expf(0.5f * ls.x);
    z.y = mu.y + nz.y * __expf(0.5f * ls.y);
    z.z = mu.z + nz.z * __expf(0.5f * ls.z);
    z.w = mu.w + nz.w * __expf(0.5f * ls.w);

    float kl = -0.5f * (nz.x*nz.x + nz.y*nz.y + nz.z*nz.z + nz.w*nz.w
                      + ls.x + ls.y + ls.z + ls.w);

    // 32 biases per row, 2 regs per lane within the 16-lane group
    float bias_r[2];
    bias_r[0] = rp[BOFF + h];
    bias_r[1] = rp[BOFF + 16 + h];

    float logacc = 0.0f;

    #pragma unroll
    for (int s = 0; s < STEPS; s++) {
        const int slot = s % STAGES;                       // literal after full unroll
        const uint32_t sb = wbase + slot * STAGE_BYTES;
        const unsigned char* sp = pipe + warp * WARP_PIPE_BYTES + slot * STAGE_BYTES;

        // oldest committed group = this stage; wait, then read our own 16B chunks
        CP_WAIT2();
        float4 u = *(const float4*)(sp + loff);
        float4 w = *(const float4*)(sp + 512 + loff);

        // refill this slot for step s+STAGES; always commit (keeps group accounting)
        if (s + STAGES < STEPS) {
            cp16(sb + loff,       Ug + (s + STAGES) * 256);
            cp16(sb + 512 + loff, Wg + (s + STAGES) * 256);
        }
        CP_COMMIT();

        // bias broadcast off the critical chain
        float bb = __shfl_sync(0xffffffffu, bias_r[s >> 4], (lane & 16) | (s & 15));

        // balanced product trees for partials
        float hl = (w.x*z.x + w.y*z.y) + (w.z*z.z + w.w*z.w);   // partial w.z
        float ul = (u.x*w.x + u.y*w.y) + (u.z*w.z + u.w*w.w);   // partial u.w

        // 4-level butterfly within each 16-lane (per-row) group
        #pragma unroll
        for (int o = 8; o > 0; o >>= 1) {
            hl += __shfl_xor_sync(0xffffffffu, hl, o);
            ul += __shfl_xor_sync(0xffffffffu, ul, o);
        }

        // tanh via fast exp: t = 1 - 2/(e^{2x}+1); correct limits at +/-inf
        float e = __expf(2.0f * (hl + bb));
        float t = 1.0f - __fdividef(2.0f, e + 1.0f);
        float x = (1.0f - t * t) * ul + 1.0f;
        logacc -= __logf(fabsf(x));

        z.x += u.x * t;  z.y += u.y * t;
        z.z += u.z * t;  z.w += u.w * t;
    }

    // coalesced float4 z write (16 lanes cover the row's 64 floats)
    ((float4*)(out + (size_t)row * LAT))[h] = z;

    // reduce kl within the 16-lane row group
    #pragma unroll
    for (int o = 8; o > 0; o >>= 1)
        kl += __shfl_xor_sync(0xffffffffu, kl, o);

    float rt = kl + logacc;                     // per-row term, uniform per 16-lane group
    rt += __shfl_xor_sync(0xffffffffu, rt, 16); // sum the warp's 2 rows

    if (lane == 0) sacc[warp] = rt;
    __syncthreads();
    if (threadIdx.x == 0) {
        float sum = 0.0f;
        #pragma unroll
        for (int i = 0; i < WARPS_PER_BLOCK; i++) sum += sacc[i];
        g_partials[blockIdx.x] = sum;
        __threadfence();
        unsigned int tk = atomicAdd(&g_count, 1u);
        is_last = (tk == NBLOCKS - 1);
    }
    __syncthreads();

    // last block reduces all partials over a FIXED tree -> deterministic
    if (is_last) {
        float v = 0.0f;
        #pragma unroll
        for (int i = threadIdx.x; i < NBLOCKS; i += NTHREADS)
            v += g_partials[i];
        #pragma unroll
        for (int o = 16; o > 0; o >>= 1)
            v += __shfl_xor_sync(0xffffffffu, v, o);
        if (lane == 0) sacc[warp] = v;
        __syncthreads();
        if (threadIdx.x == 0) {
            float sum = 0.0f;
            #pragma unroll
            for (int i = 0; i < WARPS_PER_BLOCK; i++) sum += sacc[i];
            out[out_size - 1] = sum * (1.0f / (float)BATCH);
            g_count = 0;   // reset for next graph replay
        }
    }
}

extern "C" void kernel_launch(void* const* d_in, const int* in_sizes, int n_in,
                              void* d_out, int out_size)
{
    const float* in    = (const float*)d_in[0];
    const float* noise = (const float*)d_in[1];
    float*       out   = (float*)d_out;

    // maximize smem carveout (idempotent, no allocation)
    cudaFuncSetAttribute(planar_flow_kernel,
                         cudaFuncAttributePreferredSharedMemoryCarveout, 100);

    planar_flow_kernel<<<NBLOCKS, NTHREADS>>>(in, noise, out, out_size);
}